// round 4
// baseline (speedup 1.0000x reference)
#include <cuda_runtime.h>
#include <cstdint>

// ============================================================================
// SphericalHarmonicsShellsConv — fused gather + per-voxel GEMM + CG contraction
// Shapes (fixed): B=4, N=4096, V=2048, P=32, C=16, BV=8192
// ============================================================================

#define NBV     8192
#define NGROUPS 333
#define MAXENT  4096

// ---------------- device tables (built per-launch by init kernel) -----------
__device__ float g_cg[27 * 343];          // dense real CG tensors
__device__ int2  g_e[MAXENT];             // compact entries: (ysm addr, coeff bits)
__device__ int2  g_desc[NGROUPS];         // (local out offset, J | nnz<<2 | off<<16)

// ---------------- static structure tables -----------------------------------
__constant__ unsigned char TRI_J [27] = {1,1,1, 2,2,2, 3,3, 1,1,1, 2,2,2,2, 3,3,3, 1,1, 2,2,2, 3,3,3,3};
__constant__ unsigned char TRI_L [27] = {1,1,1, 1,1,1, 1,1, 2,2,2, 2,2,2,2, 2,2,2, 3,3, 3,3,3, 3,3,3,3};
__constant__ unsigned char TRI_JO[27] = {0,1,2, 1,2,3, 2,3, 1,2,3, 0,1,2,3, 1,2,3, 2,3, 1,2,3, 0,1,2,3};

__constant__ unsigned char SEG_TYPE[34] = {0,2,2,2,  0,1,2,2,2,2,2,2,2,  0,1,2,2,2,2,2,2,2,2,2,  0,1,2,2,2,2,2,2,2,2};
__constant__ unsigned char SEG_J  [34] = {0,1,2,3,  1,0,1,2,1,2,3,2,3,  2,0,1,2,3,1,2,3,1,2,3,  3,0,2,3,1,2,3,1,2,3};
__constant__ unsigned char SEG_L  [34] = {0,1,2,3,  0,1,1,1,2,2,2,3,3,  0,2,1,1,1,2,2,2,3,3,3,  0,3,1,1,2,2,2,3,3,3};
__constant__ unsigned char SEG_CG [34] = {255,0,11,23, 255,255,1,3,8,12,15,20,24, 255,255,2,4,6,9,13,16,18,21,25, 255,255,5,7,10,14,17,19,22,26};
__constant__ unsigned char SEG_W  [34] = {4,3,2,1,  3,4,3,2,3,2,1,2,1,  2,4,3,2,1,3,2,1,3,2,1,  1,4,2,1,3,2,1,3,2,1};
__constant__ int SEGSTART[4] = {0, 4, 13, 24};
__constant__ int GROW[4]     = {10, 21, 24, 20};
__constant__ int CHJ[4]      = {160, 336, 384, 320};
__constant__ int YOFF[4]     = {0, 4, 13, 23};
__constant__ int COFF[4]     = {0, 16, 64, 144};
__constant__ long long OUT_BASE[4] = {0LL, 1310720LL, 9568256LL, 25296896LL};
__constant__ int PERBV[4]    = {160, 1008, 1920, 2240};

// ---------------- float complex helpers --------------------------------------
struct cf { float x, y; };
__device__ __forceinline__ cf cmulf(cf a, cf b) {
    return cf{a.x * b.x - a.y * b.y, a.x * b.y + a.y * b.x};
}

__device__ __forceinline__ float ffact(int n) {
    float r = 1.0f;
    for (int i = 2; i <= n; i++) r *= (float)i;
    return r;
}

__device__ float su2cgf(int j1, int m1, int j2, int m2, int j3, int m3) {
    if (m3 != m1 + m2) return 0.0f;
    int vmin = max(max(-j1 + j2 + m3, -j1 + m1), 0);
    int vmax = min(min(j2 + j3 + m1, j3 - j1 + j2), j3 + m3);
    if (vmax < vmin) return 0.0f;
    float C = sqrtf((2.0f * j3 + 1.0f) * ffact(j3 + j1 - j2) * ffact(j3 - j1 + j2) *
                    ffact(j1 + j2 - j3) * ffact(j3 + m3) * ffact(j3 - m3) /
                    (ffact(j1 + j2 + j3 + 1) * ffact(j1 - m1) * ffact(j1 + m1) *
                     ffact(j2 - m2) * ffact(j2 + m2)));
    float S = 0.0f;
    for (int v = vmin; v <= vmax; v++) {
        float t = ffact(j2 + j3 + m1 - v) * ffact(j1 - m1 + v) /
                  (ffact(v) * ffact(j3 - j1 + j2 - v) * ffact(j3 + m3 - v) *
                   ffact(v + j1 - j2 - m3));
        if ((v + j2 + m2) & 1) t = -t;
        S += t;
    }
    return C * S;
}

// q_real_to_complex entry: row r (complex m = r-l), col c (real index)
__device__ cf qentf(int l, int r, int c) {
    const float s2 = 0.70710678118654752f;
    int m = r - l;
    float re = 0.0f, im = 0.0f;
    if (m < 0) {
        if (c == l - m)      re = s2;
        else if (c == l + m) im = -s2;
    } else if (m == 0) {
        if (c == l) re = 1.0f;
    } else {
        float sg = (m & 1) ? -1.0f : 1.0f;
        if (c == l + m)      re = sg * s2;
        else if (c == l - m) im = sg * s2;
    }
    float ore, oim;
    switch (l & 3) {               // multiply by (-i)^l
        case 0:  ore = re;  oim = im;  break;
        case 1:  ore = im;  oim = -re; break;
        case 2:  ore = -re; oim = -im; break;
        default: ore = -im; oim = re;  break;
    }
    return cf{ore, oim};
}

// ---------------- combined init kernel (single block) ------------------------
// Phase A: all 27 dense real CG tensors. Phase B: compact sparse group table.
__global__ void __launch_bounds__(512) shc_init() {
    __shared__ int nnzs[NGROUPS];
    __shared__ int offs[NGROUPS];
    const int t = threadIdx.x;

    // ---- Phase A: dense CG tensors, element-parallel ----
    for (int t27 = 0; t27 < 27; t27++) {
        const int j = TRI_J[t27], l = TRI_L[t27], J = TRI_JO[t27];
        const int nj = 2 * j + 1, nl = 2 * l + 1, nJ = 2 * J + 1;
        for (int idx = t; idx < nj * nl * nJ; idx += 512) {
            int a  = idx / (nl * nJ);
            int r1 = idx % (nl * nJ);
            int b  = r1 / nJ;
            int cc = r1 % nJ;
            float ar = 0.0f;
            for (int i = 0; i < nj; i++) {
                cf q1 = qentf(j, i, a);
                if (q1.x == 0.0f && q1.y == 0.0f) continue;
                for (int k = 0; k < nl; k++) {
                    cf q2 = qentf(l, k, b);
                    if (q2.x == 0.0f && q2.y == 0.0f) continue;
                    int m1 = i - j, m2 = k - l;
                    if (abs(m1 + m2) > J) continue;
                    float s = su2cgf(j, m1, l, m2, J, m1 + m2);
                    if (s == 0.0f) continue;
                    int n = J + m1 + m2;
                    cf q3 = qentf(J, n, cc);
                    q3.y = -q3.y;                    // conj
                    cf tt = cmulf(cmulf(q1, q2), q3);
                    ar += tt.x * s;
                }
            }
            g_cg[t27 * 343 + idx] = ar;
        }
    }
    __syncthreads();

    // ---- Phase B: build compact sparse table ----
    int J = 0, local = 0;
    int   la[49];
    float lv[49];
    int nnz = 0;

    if (t < NGROUPS) {
        int base;
        if (t < 10)       { J = 0; base = 0;   }
        else if (t < 73)  { J = 1; base = 10;  }
        else if (t < 193) { J = 2; base = 73;  }
        else              { J = 3; base = 193; }
        int idx = t - base;
        int row = idx / GROW[J];
        int gr  = idx % GROW[J];
        int s = SEGSTART[J], accw = 0;
        while (gr >= accw + SEG_W[s]) { accw += SEG_W[s]; s++; }
        int u = gr - accw;
        local = row * CHJ[J] + gr * 16;

        int type = SEG_TYPE[s];
        if (type == 0) {            // l=0 copy, j=J
            la[0] = (YOFF[J] + row * (4 - J) + u) * 256;
            lv[0] = 1.0f;
            nnz = 1;
        } else if (type == 1) {     // j=0 copy, l=J
            la[0] = u * 256 + COFF[J] + row * 16;
            lv[0] = 1.0f;
            nnz = 1;
        } else {
            int jj = SEG_J[s], ll = SEG_L[s];
            const float* C = g_cg + (int)SEG_CG[s] * 343;
            int nj = 2 * jj + 1, nl2 = 2 * ll + 1, nJ = 2 * J + 1;
            for (int n = 0; n < nj; n++)
                for (int m = 0; m < nl2; m++) {
                    float v = C[(n * nl2 + m) * nJ + row];
                    if (fabsf(v) > 1e-6f) {
                        la[nnz] = (YOFF[jj] + n * (4 - jj) + u) * 256 +
                                  COFF[ll] + m * 16;
                        lv[nnz] = v;
                        nnz++;
                    }
                }
        }
        nnzs[t] = nnz;
    }
    __syncthreads();
    if (t == 0) {
        int acc = 0;
        for (int i = 0; i < NGROUPS; i++) { offs[i] = acc; acc += nnzs[i]; }
    }
    __syncthreads();
    if (t < NGROUPS) {
        int off = offs[t];
        for (int k = 0; k < nnz; k++)
            g_e[off + k] = make_int2(la[k], __float_as_int(lv[k]));
        g_desc[t] = make_int2(local, J | (nnz << 2) | (off << 16));
    }
}

// ---------------- main fused kernel -----------------------------------------
__global__ void __launch_bounds__(128, 4)
shc_main(const float* __restrict__ x0, const float* __restrict__ x1,
         const float* __restrict__ x2, const float* __restrict__ x3,
         const int*  __restrict__ pidx, const float* __restrict__ kern,
         float* __restrict__ out)
{
    __shared__ float2 ksm[32 * 32];   // [p][y], K value duplicated (k,k)
    __shared__ int    nrow[32];       // gathered flat row index b*N + n
    __shared__ float  ysm[30 * 256];  // y[yidx][c]

    const int t  = threadIdx.x;
    const int bv = blockIdx.x;

    // load K (32x30) duplicated into pairs
    const float* kb = kern + (long long)bv * 960;
    #pragma unroll
    for (int i = 0; i < 8; i++) {
        int idx = t + i * 128;
        if (idx < 960) {
            float v = kb[idx];
            int p = idx / 30, y = idx - p * 30;
            ksm[p * 32 + y] = make_float2(v, v);
        }
    }
    if (t < 32) {
        int2 pr = ((const int2*)pidx)[(long long)bv * 32 + t];
        nrow[t] = pr.x * 4096 + pr.y;
    }
    __syncthreads();

    // this thread's two adjacent channels c, c+1 (pairs never straddle arrays)
    const int c = t * 2;
    const float* src; int chl;
    if (c < 16)       { src = x0 + c;         chl = 16;  }
    else if (c < 64)  { src = x1 + (c - 16);  chl = 48;  }
    else if (c < 144) { src = x2 + (c - 64);  chl = 80;  }
    else              { src = x3 + (c - 144); chl = 112; }

    unsigned long long acc[30];
    #pragma unroll
    for (int y = 0; y < 30; y++) acc[y] = 0ull;

    // gather pipeline, depth 4 (MLP=4 hides L2/DRAM latency)
    unsigned long long sbuf[4];
    #pragma unroll
    for (int i = 0; i < 4; i++)
        sbuf[i] = *reinterpret_cast<const unsigned long long*>(
                      src + (long long)nrow[i] * chl);

    #pragma unroll 8
    for (int p = 0; p < 32; p++) {
        unsigned long long s = sbuf[p & 3];
        if (p + 4 < 32)
            sbuf[p & 3] = *reinterpret_cast<const unsigned long long*>(
                              src + (long long)nrow[p + 4] * chl);
        const ulonglong2* kp = reinterpret_cast<const ulonglong2*>(&ksm[p * 32]);
        #pragma unroll
        for (int h = 0; h < 15; h++) {
            ulonglong2 k2 = kp[h];
            asm("fma.rn.f32x2 %0, %1, %2, %0;" : "+l"(acc[2 * h])     : "l"(s), "l"(k2.x));
            asm("fma.rn.f32x2 %0, %1, %2, %0;" : "+l"(acc[2 * h + 1]) : "l"(s), "l"(k2.y));
        }
    }
    #pragma unroll
    for (int y = 0; y < 30; y++)
        *reinterpret_cast<unsigned long long*>(&ysm[y * 256 + c]) = acc[y];
    __syncthreads();

    // stage 2: sparse CG contraction + copies (compact table, L1-resident,
    // 4-wide independent load batches)
    const int ch = t & 15;
    for (int g = (t >> 4); g < NGROUPS; g += 8) {
        int2 d = __ldg(&g_desc[g]);
        int J   = d.y & 3;
        int nnz = (d.y >> 2) & 63;
        int off = d.y >> 16;
        float v = 0.0f;
        int k = 0;
        for (; k + 4 <= nnz; k += 4) {
            int2 e0 = __ldg(&g_e[off + k]);
            int2 e1 = __ldg(&g_e[off + k + 1]);
            int2 e2 = __ldg(&g_e[off + k + 2]);
            int2 e3 = __ldg(&g_e[off + k + 3]);
            float y0 = ysm[e0.x + ch], y1 = ysm[e1.x + ch];
            float y2 = ysm[e2.x + ch], y3 = ysm[e3.x + ch];
            float v0 = __int_as_float(e0.y) * y0;
            float v1 = __int_as_float(e1.y) * y1;
            v0 = fmaf(__int_as_float(e2.y), y2, v0);
            v1 = fmaf(__int_as_float(e3.y), y3, v1);
            v += v0 + v1;
        }
        for (; k < nnz; k++) {
            int2 e = __ldg(&g_e[off + k]);
            v = fmaf(__int_as_float(e.y), ysm[e.x + ch], v);
        }
        out[OUT_BASE[J] + (long long)bv * PERBV[J] + d.x + ch] = v;
    }
}

// ---------------- launch -----------------------------------------------------
extern "C" void kernel_launch(void* const* d_in, const int* in_sizes, int n_in,
                              void* d_out, int out_size)
{
    const float* x0   = (const float*)d_in[0];
    const float* x1   = (const float*)d_in[1];
    const float* x2   = (const float*)d_in[2];
    const float* x3   = (const float*)d_in[3];
    const int*   pidx = (const int*)  d_in[4];
    const float* kern = (const float*)d_in[5];
    float* out = (float*)d_out;

    shc_init<<<1, 512>>>();
    shc_main<<<NBV, 128>>>(x0, x1, x2, x3, pidx, kern, out);
}

// round 5
// speedup vs baseline: 1.2979x; 1.2979x over previous
#include <cuda_runtime.h>
#include <cstdint>

// ============================================================================
// SphericalHarmonicsShellsConv — fused gather + per-voxel GEMM + CG contraction
// Shapes (fixed): B=4, N=4096, V=2048, P=32, C=16, BV=8192
// ============================================================================

#define NBV     8192
#define NGROUPS 333
#define MAXENT  4096

// ---------------- device tables (built per-launch by init kernels) ----------
__device__ float g_cg[27 * 343];          // dense real CG tensors
__device__ int2  g_e[MAXENT];             // compact entries: (ysm addr, coeff bits)
__device__ int2  g_desc[NGROUPS];         // (local out offset, J | nnz<<2 | off<<16)

// ---------------- static structure tables -----------------------------------
__constant__ unsigned char TRI_J [27] = {1,1,1, 2,2,2, 3,3, 1,1,1, 2,2,2,2, 3,3,3, 1,1, 2,2,2, 3,3,3,3};
__constant__ unsigned char TRI_L [27] = {1,1,1, 1,1,1, 1,1, 2,2,2, 2,2,2,2, 2,2,2, 3,3, 3,3,3, 3,3,3,3};
__constant__ unsigned char TRI_JO[27] = {0,1,2, 1,2,3, 2,3, 1,2,3, 0,1,2,3, 1,2,3, 2,3, 1,2,3, 0,1,2,3};

__constant__ unsigned char SEG_TYPE[34] = {0,2,2,2,  0,1,2,2,2,2,2,2,2,  0,1,2,2,2,2,2,2,2,2,2,  0,1,2,2,2,2,2,2,2,2};
__constant__ unsigned char SEG_J  [34] = {0,1,2,3,  1,0,1,2,1,2,3,2,3,  2,0,1,2,3,1,2,3,1,2,3,  3,0,2,3,1,2,3,1,2,3};
__constant__ unsigned char SEG_L  [34] = {0,1,2,3,  0,1,1,1,2,2,2,3,3,  0,2,1,1,1,2,2,2,3,3,3,  0,3,1,1,2,2,2,3,3,3};
__constant__ unsigned char SEG_CG [34] = {255,0,11,23, 255,255,1,3,8,12,15,20,24, 255,255,2,4,6,9,13,16,18,21,25, 255,255,5,7,10,14,17,19,22,26};
__constant__ unsigned char SEG_W  [34] = {4,3,2,1,  3,4,3,2,3,2,1,2,1,  2,4,3,2,1,3,2,1,3,2,1,  1,4,2,1,3,2,1,3,2,1};
__constant__ int SEGSTART[4] = {0, 4, 13, 24};
__constant__ int GROW[4]     = {10, 21, 24, 20};
__constant__ int CHJ[4]      = {160, 336, 384, 320};
__constant__ int YOFF[4]     = {0, 4, 13, 23};
__constant__ int COFF[4]     = {0, 16, 64, 144};
__constant__ long long OUT_BASE[4] = {0LL, 1310720LL, 9568256LL, 25296896LL};
__constant__ int PERBV[4]    = {160, 1008, 1920, 2240};

// ---------------- float complex helpers --------------------------------------
struct cf { float x, y; };
__device__ __forceinline__ cf cmulf(cf a, cf b) {
    return cf{a.x * b.x - a.y * b.y, a.x * b.y + a.y * b.x};
}

__device__ __forceinline__ float ffact(int n) {
    float r = 1.0f;
    for (int i = 2; i <= n; i++) r *= (float)i;
    return r;
}

__device__ float su2cgf(int j1, int m1, int j2, int m2, int j3, int m3) {
    if (m3 != m1 + m2) return 0.0f;
    int vmin = max(max(-j1 + j2 + m3, -j1 + m1), 0);
    int vmax = min(min(j2 + j3 + m1, j3 - j1 + j2), j3 + m3);
    if (vmax < vmin) return 0.0f;
    float C = sqrtf((2.0f * j3 + 1.0f) * ffact(j3 + j1 - j2) * ffact(j3 - j1 + j2) *
                    ffact(j1 + j2 - j3) * ffact(j3 + m3) * ffact(j3 - m3) /
                    (ffact(j1 + j2 + j3 + 1) * ffact(j1 - m1) * ffact(j1 + m1) *
                     ffact(j2 - m2) * ffact(j2 + m2)));
    float S = 0.0f;
    for (int v = vmin; v <= vmax; v++) {
        float t = ffact(j2 + j3 + m1 - v) * ffact(j1 - m1 + v) /
                  (ffact(v) * ffact(j3 - j1 + j2 - v) * ffact(j3 + m3 - v) *
                   ffact(v + j1 - j2 - m3));
        if ((v + j2 + m2) & 1) t = -t;
        S += t;
    }
    return C * S;
}

// q_real_to_complex entry: row r (complex m = r-l), col c (real index)
__device__ cf qentf(int l, int r, int c) {
    const float s2 = 0.70710678118654752f;
    int m = r - l;
    float re = 0.0f, im = 0.0f;
    if (m < 0) {
        if (c == l - m)      re = s2;
        else if (c == l + m) im = -s2;
    } else if (m == 0) {
        if (c == l) re = 1.0f;
    } else {
        float sg = (m & 1) ? -1.0f : 1.0f;
        if (c == l + m)      re = sg * s2;
        else if (c == l - m) im = sg * s2;
    }
    float ore, oim;
    switch (l & 3) {               // multiply by (-i)^l
        case 0:  ore = re;  oim = im;  break;
        case 1:  ore = im;  oim = -re; break;
        case 2:  ore = -re; oim = -im; break;
        default: ore = -im; oim = re;  break;
    }
    return cf{ore, oim};
}

// ---------------- init kernel 1: dense real CG tensors (float, 27 blocks) ---
__global__ void shc_init_cg() {
    const int t27 = blockIdx.x;
    const int j = TRI_J[t27], l = TRI_L[t27], J = TRI_JO[t27];
    const int nj = 2 * j + 1, nl = 2 * l + 1, nJ = 2 * J + 1;
    __shared__ float su2[7][7];

    for (int idx = threadIdx.x; idx < nj * nl; idx += blockDim.x) {
        int i = idx / nl, k = idx % nl;
        int m1 = i - j, m2 = k - l, m3 = m1 + m2;
        su2[i][k] = (abs(m3) <= J) ? su2cgf(j, m1, l, m2, J, m3) : 0.0f;
    }
    __syncthreads();

    for (int idx = threadIdx.x; idx < nj * nl * nJ; idx += blockDim.x) {
        int a  = idx / (nl * nJ);
        int r1 = idx % (nl * nJ);
        int b  = r1 / nJ;
        int cc = r1 % nJ;
        float ar = 0.0f;
        for (int i = 0; i < nj; i++) {
            cf q1 = qentf(j, i, a);
            if (q1.x == 0.0f && q1.y == 0.0f) continue;
            for (int k = 0; k < nl; k++) {
                float s = su2[i][k];
                if (s == 0.0f) continue;
                cf q2 = qentf(l, k, b);
                if (q2.x == 0.0f && q2.y == 0.0f) continue;
                int n = J + (i - j) + (k - l);
                cf q3 = qentf(J, n, cc);
                q3.y = -q3.y;                    // conj
                cf tt = cmulf(cmulf(q1, q2), q3);
                ar += tt.x * s;
            }
        }
        g_cg[t27 * 343 + idx] = ar;
    }
}

// ---------------- init kernel 2: compact sparse group table ------------------
__global__ void shc_build_table() {
    __shared__ int nnzs[NGROUPS];
    __shared__ int offs[NGROUPS];

    const int g = threadIdx.x;
    int J = 0, local = 0;
    int   la[49];
    float lv[49];
    int nnz = 0;

    if (g < NGROUPS) {
        int base;
        if (g < 10)       { J = 0; base = 0;   }
        else if (g < 73)  { J = 1; base = 10;  }
        else if (g < 193) { J = 2; base = 73;  }
        else              { J = 3; base = 193; }
        int idx = g - base;
        int row = idx / GROW[J];
        int gr  = idx % GROW[J];
        int s = SEGSTART[J], accw = 0;
        while (gr >= accw + SEG_W[s]) { accw += SEG_W[s]; s++; }
        int u = gr - accw;
        local = row * CHJ[J] + gr * 16;

        int type = SEG_TYPE[s];
        if (type == 0) {            // l=0 copy, j=J
            la[0] = (YOFF[J] + row * (4 - J) + u) * 256;
            lv[0] = 1.0f;
            nnz = 1;
        } else if (type == 1) {     // j=0 copy, l=J
            la[0] = u * 256 + COFF[J] + row * 16;
            lv[0] = 1.0f;
            nnz = 1;
        } else {
            int jj = SEG_J[s], ll = SEG_L[s];
            const float* C = g_cg + (int)SEG_CG[s] * 343;
            int nj = 2 * jj + 1, nl2 = 2 * ll + 1, nJ = 2 * J + 1;
            for (int n = 0; n < nj; n++)
                for (int m = 0; m < nl2; m++) {
                    float v = C[(n * nl2 + m) * nJ + row];
                    if (fabsf(v) > 1e-6f) {
                        la[nnz] = (YOFF[jj] + n * (4 - jj) + u) * 256 +
                                  COFF[ll] + m * 16;
                        lv[nnz] = v;
                        nnz++;
                    }
                }
        }
        nnzs[g] = nnz;
    }
    __syncthreads();
    if (threadIdx.x == 0) {
        int acc = 0;
        for (int i = 0; i < NGROUPS; i++) { offs[i] = acc; acc += nnzs[i]; }
    }
    __syncthreads();
    if (g < NGROUPS) {
        int off = offs[g];
        for (int k = 0; k < nnz; k++)
            g_e[off + k] = make_int2(la[k], __float_as_int(lv[k]));
        g_desc[g] = make_int2(local, J | (nnz << 2) | (off << 16));
    }
}

// ---------------- main fused kernel -----------------------------------------
// Two y-passes (y 0..15, y 16..29) keep accumulator footprint at 32/28 regs
// so the whole kernel fits in ~100 regs — no local-memory spills.
__global__ void __launch_bounds__(128, 4)
shc_main(const float* __restrict__ x0, const float* __restrict__ x1,
         const float* __restrict__ x2, const float* __restrict__ x3,
         const int*  __restrict__ pidx, const float* __restrict__ kern,
         float* __restrict__ out)
{
    __shared__ float2 ksm[32 * 32];   // [p][y], K value duplicated (k,k), padded to 32
    __shared__ int    nrow[32];       // gathered flat row index b*N + n
    __shared__ float  ysm[30 * 256];  // y[yidx][c]

    const int t  = threadIdx.x;
    const int bv = blockIdx.x;

    // load K (32x30) duplicated into pairs
    const float* kb = kern + (long long)bv * 960;
    #pragma unroll
    for (int i = 0; i < 8; i++) {
        int idx = t + i * 128;
        if (idx < 960) {
            float v = kb[idx];
            int p = idx / 30, y = idx - p * 30;
            ksm[p * 32 + y] = make_float2(v, v);
        }
    }
    if (t < 32) {
        int2 pr = ((const int2*)pidx)[(long long)bv * 32 + t];
        nrow[t] = pr.x * 4096 + pr.y;
    }
    __syncthreads();

    // this thread's two adjacent channels c, c+1 (pairs never straddle arrays)
    const int c = t * 2;
    const float* src; int chl;
    if (c < 16)       { src = x0 + c;         chl = 16;  }
    else if (c < 64)  { src = x1 + (c - 16);  chl = 48;  }
    else if (c < 144) { src = x2 + (c - 64);  chl = 80;  }
    else              { src = x3 + (c - 144); chl = 112; }

    // ---------- pass 0: y = 0..15 ----------
    {
        unsigned long long acc[16];
        #pragma unroll
        for (int y = 0; y < 16; y++) acc[y] = 0ull;

        unsigned long long sbuf[4];
        #pragma unroll
        for (int i = 0; i < 4; i++)
            sbuf[i] = *reinterpret_cast<const unsigned long long*>(
                          src + (long long)nrow[i] * chl);

        #pragma unroll 2
        for (int p = 0; p < 32; p++) {
            unsigned long long s = sbuf[p & 3];
            if (p + 4 < 32)
                sbuf[p & 3] = *reinterpret_cast<const unsigned long long*>(
                                  src + (long long)nrow[p + 4] * chl);
            const ulonglong2* kp = reinterpret_cast<const ulonglong2*>(&ksm[p * 32]);
            #pragma unroll
            for (int h = 0; h < 8; h++) {
                ulonglong2 k2 = kp[h];
                asm("fma.rn.f32x2 %0, %1, %2, %0;" : "+l"(acc[2 * h])     : "l"(s), "l"(k2.x));
                asm("fma.rn.f32x2 %0, %1, %2, %0;" : "+l"(acc[2 * h + 1]) : "l"(s), "l"(k2.y));
            }
        }
        #pragma unroll
        for (int y = 0; y < 16; y++)
            *reinterpret_cast<unsigned long long*>(&ysm[y * 256 + c]) = acc[y];
    }

    // ---------- pass 1: y = 16..29 ----------
    {
        unsigned long long acc[14];
        #pragma unroll
        for (int y = 0; y < 14; y++) acc[y] = 0ull;

        unsigned long long sbuf[4];
        #pragma unroll
        for (int i = 0; i < 4; i++)
            sbuf[i] = *reinterpret_cast<const unsigned long long*>(
                          src + (long long)nrow[i] * chl);

        #pragma unroll 2
        for (int p = 0; p < 32; p++) {
            unsigned long long s = sbuf[p & 3];
            if (p + 4 < 32)
                sbuf[p & 3] = *reinterpret_cast<const unsigned long long*>(
                                  src + (long long)nrow[p + 4] * chl);
            const ulonglong2* kp = reinterpret_cast<const ulonglong2*>(&ksm[p * 32]);
            #pragma unroll
            for (int h = 0; h < 7; h++) {
                ulonglong2 k2 = kp[8 + h];
                asm("fma.rn.f32x2 %0, %1, %2, %0;" : "+l"(acc[2 * h])     : "l"(s), "l"(k2.x));
                asm("fma.rn.f32x2 %0, %1, %2, %0;" : "+l"(acc[2 * h + 1]) : "l"(s), "l"(k2.y));
            }
        }
        #pragma unroll
        for (int y = 0; y < 14; y++)
            *reinterpret_cast<unsigned long long*>(&ysm[(16 + y) * 256 + c]) = acc[y];
    }
    __syncthreads();

    // stage 2: sparse CG contraction + copies (compact table, L1-resident,
    // 4-wide independent load batches)
    const int ch = t & 15;
    for (int g = (t >> 4); g < NGROUPS; g += 8) {
        int2 d = __ldg(&g_desc[g]);
        int J   = d.y & 3;
        int nnz = (d.y >> 2) & 63;
        int off = d.y >> 16;
        float v = 0.0f;
        int k = 0;
        for (; k + 4 <= nnz; k += 4) {
            int2 e0 = __ldg(&g_e[off + k]);
            int2 e1 = __ldg(&g_e[off + k + 1]);
            int2 e2 = __ldg(&g_e[off + k + 2]);
            int2 e3 = __ldg(&g_e[off + k + 3]);
            float y0 = ysm[e0.x + ch], y1 = ysm[e1.x + ch];
            float y2 = ysm[e2.x + ch], y3 = ysm[e3.x + ch];
            float v0 = __int_as_float(e0.y) * y0;
            float v1 = __int_as_float(e1.y) * y1;
            v0 = fmaf(__int_as_float(e2.y), y2, v0);
            v1 = fmaf(__int_as_float(e3.y), y3, v1);
            v += v0 + v1;
        }
        for (; k < nnz; k++) {
            int2 e = __ldg(&g_e[off + k]);
            v = fmaf(__int_as_float(e.y), ysm[e.x + ch], v);
        }
        out[OUT_BASE[J] + (long long)bv * PERBV[J] + d.x + ch] = v;
    }
}

// ---------------- launch -----------------------------------------------------
extern "C" void kernel_launch(void* const* d_in, const int* in_sizes, int n_in,
                              void* d_out, int out_size)
{
    const float* x0   = (const float*)d_in[0];
    const float* x1   = (const float*)d_in[1];
    const float* x2   = (const float*)d_in[2];
    const float* x3   = (const float*)d_in[3];
    const int*   pidx = (const int*)  d_in[4];
    const float* kern = (const float*)d_in[5];
    float* out = (float*)d_out;

    shc_init_cg<<<27, 128>>>();
    shc_build_table<<<1, 352>>>();
    shc_main<<<NBV, 128>>>(x0, x1, x2, x3, pidx, kern, out);
}

// round 6
// speedup vs baseline: 1.6533x; 1.2738x over previous
#include <cuda_runtime.h>
#include <cstdint>

// ============================================================================
// SphericalHarmonicsShellsConv — fused gather + per-voxel GEMM + CG contraction
// Shapes (fixed): B=4, N=4096, V=2048, P=32, C=16, BV=8192
// ============================================================================

#define NBV     8192
#define NGROUPS 333
#define MAXENT  4096

// ---------------- device tables (built per-launch by init kernels) ----------
__device__ float g_cg[27 * 343];                    // dense real CG tensors
__device__ __align__(16) int2 g_e[MAXENT];          // entries: (ysm addr, coeff bits)
__device__ int2  g_desc[NGROUPS];                   // (local out off, J | nnz<<2 | off<<16)

// ---------------- static structure tables -----------------------------------
__constant__ unsigned char TRI_J [27] = {1,1,1, 2,2,2, 3,3, 1,1,1, 2,2,2,2, 3,3,3, 1,1, 2,2,2, 3,3,3,3};
__constant__ unsigned char TRI_L [27] = {1,1,1, 1,1,1, 1,1, 2,2,2, 2,2,2,2, 2,2,2, 3,3, 3,3,3, 3,3,3,3};
__constant__ unsigned char TRI_JO[27] = {0,1,2, 1,2,3, 2,3, 1,2,3, 0,1,2,3, 1,2,3, 2,3, 1,2,3, 0,1,2,3};

__constant__ unsigned char SEG_TYPE[34] = {0,2,2,2,  0,1,2,2,2,2,2,2,2,  0,1,2,2,2,2,2,2,2,2,2,  0,1,2,2,2,2,2,2,2,2};
__constant__ unsigned char SEG_J  [34] = {0,1,2,3,  1,0,1,2,1,2,3,2,3,  2,0,1,2,3,1,2,3,1,2,3,  3,0,2,3,1,2,3,1,2,3};
__constant__ unsigned char SEG_L  [34] = {0,1,2,3,  0,1,1,1,2,2,2,3,3,  0,2,1,1,1,2,2,2,3,3,3,  0,3,1,1,2,2,2,3,3,3};
__constant__ unsigned char SEG_CG [34] = {255,0,11,23, 255,255,1,3,8,12,15,20,24, 255,255,2,4,6,9,13,16,18,21,25, 255,255,5,7,10,14,17,19,22,26};
__constant__ unsigned char SEG_W  [34] = {4,3,2,1,  3,4,3,2,3,2,1,2,1,  2,4,3,2,1,3,2,1,3,2,1,  1,4,2,1,3,2,1,3,2,1};
__constant__ int SEGSTART[4] = {0, 4, 13, 24};
__constant__ int GROW[4]     = {10, 21, 24, 20};
__constant__ int CHJ[4]      = {160, 336, 384, 320};
__constant__ int YOFF[4]     = {0, 4, 13, 23};
__constant__ int COFF[4]     = {0, 16, 64, 144};
__constant__ long long OUT_BASE[4] = {0LL, 1310720LL, 9568256LL, 25296896LL};
__constant__ int PERBV[4]    = {160, 1008, 1920, 2240};

// ---------------- float complex helpers --------------------------------------
struct cf { float x, y; };
__device__ __forceinline__ cf cmulf(cf a, cf b) {
    return cf{a.x * b.x - a.y * b.y, a.x * b.y + a.y * b.x};
}

__device__ __forceinline__ float ffact(int n) {
    float r = 1.0f;
    for (int i = 2; i <= n; i++) r *= (float)i;
    return r;
}

__device__ float su2cgf(int j1, int m1, int j2, int m2, int j3, int m3) {
    if (m3 != m1 + m2) return 0.0f;
    int vmin = max(max(-j1 + j2 + m3, -j1 + m1), 0);
    int vmax = min(min(j2 + j3 + m1, j3 - j1 + j2), j3 + m3);
    if (vmax < vmin) return 0.0f;
    float C = sqrtf((2.0f * j3 + 1.0f) * ffact(j3 + j1 - j2) * ffact(j3 - j1 + j2) *
                    ffact(j1 + j2 - j3) * ffact(j3 + m3) * ffact(j3 - m3) /
                    (ffact(j1 + j2 + j3 + 1) * ffact(j1 - m1) * ffact(j1 + m1) *
                     ffact(j2 - m2) * ffact(j2 + m2)));
    float S = 0.0f;
    for (int v = vmin; v <= vmax; v++) {
        float t = ffact(j2 + j3 + m1 - v) * ffact(j1 - m1 + v) /
                  (ffact(v) * ffact(j3 - j1 + j2 - v) * ffact(j3 + m3 - v) *
                   ffact(v + j1 - j2 - m3));
        if ((v + j2 + m2) & 1) t = -t;
        S += t;
    }
    return C * S;
}

// q_real_to_complex entry: row r (complex m = r-l), col c (real index)
__device__ cf qentf(int l, int r, int c) {
    const float s2 = 0.70710678118654752f;
    int m = r - l;
    float re = 0.0f, im = 0.0f;
    if (m < 0) {
        if (c == l - m)      re = s2;
        else if (c == l + m) im = -s2;
    } else if (m == 0) {
        if (c == l) re = 1.0f;
    } else {
        float sg = (m & 1) ? -1.0f : 1.0f;
        if (c == l + m)      re = sg * s2;
        else if (c == l - m) im = sg * s2;
    }
    float ore, oim;
    switch (l & 3) {               // multiply by (-i)^l
        case 0:  ore = re;  oim = im;  break;
        case 1:  ore = im;  oim = -re; break;
        case 2:  ore = -re; oim = -im; break;
        default: ore = -im; oim = re;  break;
    }
    return cf{ore, oim};
}

// ---------------- init kernel 1: dense real CG tensors (float, 27 blocks) ---
__global__ void shc_init_cg() {
    const int t27 = blockIdx.x;
    const int j = TRI_J[t27], l = TRI_L[t27], J = TRI_JO[t27];
    const int nj = 2 * j + 1, nl = 2 * l + 1, nJ = 2 * J + 1;
    __shared__ float su2[7][7];

    for (int idx = threadIdx.x; idx < nj * nl; idx += blockDim.x) {
        int i = idx / nl, k = idx % nl;
        int m1 = i - j, m2 = k - l, m3 = m1 + m2;
        su2[i][k] = (abs(m3) <= J) ? su2cgf(j, m1, l, m2, J, m3) : 0.0f;
    }
    __syncthreads();

    for (int idx = threadIdx.x; idx < nj * nl * nJ; idx += blockDim.x) {
        int a  = idx / (nl * nJ);
        int r1 = idx % (nl * nJ);
        int b  = r1 / nJ;
        int cc = r1 % nJ;
        float ar = 0.0f;
        for (int i = 0; i < nj; i++) {
            cf q1 = qentf(j, i, a);
            if (q1.x == 0.0f && q1.y == 0.0f) continue;
            for (int k = 0; k < nl; k++) {
                float s = su2[i][k];
                if (s == 0.0f) continue;
                cf q2 = qentf(l, k, b);
                if (q2.x == 0.0f && q2.y == 0.0f) continue;
                int n = J + (i - j) + (k - l);
                cf q3 = qentf(J, n, cc);
                q3.y = -q3.y;                    // conj
                cf tt = cmulf(cmulf(q1, q2), q3);
                ar += tt.x * s;
            }
        }
        g_cg[t27 * 343 + idx] = ar;
    }
}

// ---------------- init kernel 2: compact sparse group table ------------------
// Each group's entry list is padded to an even count so the main kernel can
// read entries as int4 (two entries per LDG.128).
__global__ void shc_build_table() {
    __shared__ int nnzs[NGROUPS];
    __shared__ int offs[NGROUPS];

    const int g = threadIdx.x;
    int J = 0, local = 0;
    int   la[50];
    float lv[50];
    int nnz = 0;

    if (g < NGROUPS) {
        int base;
        if (g < 10)       { J = 0; base = 0;   }
        else if (g < 73)  { J = 1; base = 10;  }
        else if (g < 193) { J = 2; base = 73;  }
        else              { J = 3; base = 193; }
        int idx = g - base;
        int row = idx / GROW[J];
        int gr  = idx % GROW[J];
        int s = SEGSTART[J], accw = 0;
        while (gr >= accw + SEG_W[s]) { accw += SEG_W[s]; s++; }
        int u = gr - accw;
        local = row * CHJ[J] + gr * 16;

        int type = SEG_TYPE[s];
        if (type == 0) {            // l=0 copy, j=J
            la[0] = (YOFF[J] + row * (4 - J) + u) * 256;
            lv[0] = 1.0f;
            nnz = 1;
        } else if (type == 1) {     // j=0 copy, l=J
            la[0] = u * 256 + COFF[J] + row * 16;
            lv[0] = 1.0f;
            nnz = 1;
        } else {
            int jj = SEG_J[s], ll = SEG_L[s];
            const float* C = g_cg + (int)SEG_CG[s] * 343;
            int nj = 2 * jj + 1, nl2 = 2 * ll + 1, nJ = 2 * J + 1;
            for (int n = 0; n < nj; n++)
                for (int m = 0; m < nl2; m++) {
                    float v = C[(n * nl2 + m) * nJ + row];
                    if (fabsf(v) > 1e-6f) {
                        la[nnz] = (YOFF[jj] + n * (4 - jj) + u) * 256 +
                                  COFF[ll] + m * 16;
                        lv[nnz] = v;
                        nnz++;
                    }
                }
        }
        if (nnz & 1) { la[nnz] = 0; lv[nnz] = 0.0f; nnz++; }   // pad to even
        nnzs[g] = nnz;
    }
    __syncthreads();
    if (threadIdx.x == 0) {
        int acc = 0;
        for (int i = 0; i < NGROUPS; i++) { offs[i] = acc; acc += nnzs[i]; }
    }
    __syncthreads();
    if (g < NGROUPS) {
        int off = offs[g];                       // even (sum of evens)
        for (int k = 0; k < nnz; k++)
            g_e[off + k] = make_int2(la[k], __float_as_int(lv[k]));
        g_desc[g] = make_int2(local, J | (nnz << 2) | (off << 16));
    }
}

// ---------------- main fused kernel -----------------------------------------
// smem layout: ysm[30*256] floats (30720 B). During stage 1, the first 8320 B
// of the same buffer hold ksm (32x32 float2 = 8192 B) + nrow (128 B); a
// barrier separates the last read of ksm/nrow from the ysm stores.
__global__ void __launch_bounds__(128, 6)
shc_main(const float* __restrict__ x0, const float* __restrict__ x1,
         const float* __restrict__ x2, const float* __restrict__ x3,
         const int*  __restrict__ pidx, const float* __restrict__ kern,
         float* __restrict__ out)
{
    __shared__ __align__(16) char smraw[30 * 256 * 4];
    float*  ysm  = reinterpret_cast<float*>(smraw);
    float2* ksm  = reinterpret_cast<float2*>(smraw);           // [p][y] dup (k,k)
    int*    nrow = reinterpret_cast<int*>(smraw + 8192);       // 32 ints

    const int t  = threadIdx.x;
    const int bv = blockIdx.x;

    // load K (32x30) duplicated into pairs
    const float* kb = kern + (long long)bv * 960;
    #pragma unroll
    for (int i = 0; i < 8; i++) {
        int idx = t + i * 128;
        if (idx < 960) {
            float v = kb[idx];
            int p = idx / 30, y = idx - p * 30;
            ksm[p * 32 + y] = make_float2(v, v);
        }
    }
    if (t < 32) {
        int2 pr = ((const int2*)pidx)[(long long)bv * 32 + t];
        nrow[t] = pr.x * 4096 + pr.y;
    }
    __syncthreads();

    // this thread's two adjacent channels c, c+1 (pairs never straddle arrays)
    const int c = t * 2;
    const float* src; int chl;
    if (c < 16)       { src = x0 + c;         chl = 16;  }
    else if (c < 64)  { src = x1 + (c - 16);  chl = 48;  }
    else if (c < 144) { src = x2 + (c - 64);  chl = 80;  }
    else              { src = x3 + (c - 144); chl = 112; }

    unsigned long long acc[30];
    #pragma unroll
    for (int y = 0; y < 30; y++) acc[y] = 0ull;

    // depth-2 pipelined gather + packed FMA (two rows per iteration)
    unsigned long long s0 = *reinterpret_cast<const unsigned long long*>(
                                src + (long long)nrow[0] * chl);
    unsigned long long s1 = *reinterpret_cast<const unsigned long long*>(
                                src + (long long)nrow[1] * chl);
    #pragma unroll 2
    for (int p = 0; p < 32; p += 2) {
        unsigned long long a = s0, b = s1;
        if (p + 2 < 32) {
            s0 = *reinterpret_cast<const unsigned long long*>(
                     src + (long long)nrow[p + 2] * chl);
            s1 = *reinterpret_cast<const unsigned long long*>(
                     src + (long long)nrow[p + 3] * chl);
        }
        const ulonglong2* kpa = reinterpret_cast<const ulonglong2*>(&ksm[p * 32]);
        const ulonglong2* kpb = reinterpret_cast<const ulonglong2*>(&ksm[(p + 1) * 32]);
        #pragma unroll
        for (int h = 0; h < 15; h++) {
            ulonglong2 k2a = kpa[h];
            asm("fma.rn.f32x2 %0, %1, %2, %0;" : "+l"(acc[2 * h])     : "l"(a), "l"(k2a.x));
            asm("fma.rn.f32x2 %0, %1, %2, %0;" : "+l"(acc[2 * h + 1]) : "l"(a), "l"(k2a.y));
        }
        #pragma unroll
        for (int h = 0; h < 15; h++) {
            ulonglong2 k2b = kpb[h];
            asm("fma.rn.f32x2 %0, %1, %2, %0;" : "+l"(acc[2 * h])     : "l"(b), "l"(k2b.x));
            asm("fma.rn.f32x2 %0, %1, %2, %0;" : "+l"(acc[2 * h + 1]) : "l"(b), "l"(k2b.y));
        }
    }

    __syncthreads();   // all ksm/nrow reads done — safe to overwrite with ysm

    #pragma unroll
    for (int y = 0; y < 30; y++)
        *reinterpret_cast<unsigned long long*>(&ysm[y * 256 + c]) = acc[y];
    __syncthreads();

    // stage 2: sparse CG contraction + copies (int4 = 2 entries per load)
    const int ch = t & 15;
    const int4* e4 = reinterpret_cast<const int4*>(g_e);
    for (int g = (t >> 4); g < NGROUPS; g += 8) {
        int2 d = __ldg(&g_desc[g]);
        int J    = d.y & 3;
        int npair = ((d.y >> 2) & 63) >> 1;
        int base4 = (d.y >> 16) >> 1;
        float v = 0.0f;
        int k = 0;
        for (; k + 2 <= npair; k += 2) {
            int4 pA = __ldg(&e4[base4 + k]);
            int4 pB = __ldg(&e4[base4 + k + 1]);
            float v0 = __int_as_float(pA.y) * ysm[pA.x + ch];
            float v1 = __int_as_float(pA.w) * ysm[pA.z + ch];
            v0 = fmaf(__int_as_float(pB.y), ysm[pB.x + ch], v0);
            v1 = fmaf(__int_as_float(pB.w), ysm[pB.z + ch], v1);
            v += v0 + v1;
        }
        if (k < npair) {
            int4 pA = __ldg(&e4[base4 + k]);
            v = fmaf(__int_as_float(pA.y), ysm[pA.x + ch], v);
            v = fmaf(__int_as_float(pA.w), ysm[pA.z + ch], v);
        }
        out[OUT_BASE[J] + (long long)bv * PERBV[J] + d.x + ch] = v;
    }
}

// ---------------- launch -----------------------------------------------------
extern "C" void kernel_launch(void* const* d_in, const int* in_sizes, int n_in,
                              void* d_out, int out_size)
{
    const float* x0   = (const float*)d_in[0];
    const float* x1   = (const float*)d_in[1];
    const float* x2   = (const float*)d_in[2];
    const float* x3   = (const float*)d_in[3];
    const int*   pidx = (const int*)  d_in[4];
    const float* kern = (const float*)d_in[5];
    float* out = (float*)d_out;

    shc_init_cg<<<27, 128>>>();
    shc_build_table<<<1, 352>>>();
    shc_main<<<NBV, 128>>>(x0, x1, x2, x3, pidx, kern, out);
}

// round 7
// speedup vs baseline: 2.1210x; 1.2829x over previous
#include <cuda_runtime.h>
#include <cstdint>

// ============================================================================
// SphericalHarmonicsShellsConv — fused gather + per-voxel GEMM + CG contraction
// Shapes (fixed): B=4, N=4096, V=2048, P=32, C=16, BV=8192
//
// Block = 256 threads: thread t -> channel pair q = t&127 (c = 2q), y-half
// h2 = t>>7 (y 16*h2 .. 16*h2+15, K padded to 32 y's with zeros).
// 16 packed accumulators per thread => ~56 regs, no spills, 4 blocks/SM.
// ============================================================================

#define NBV     8192
#define NGROUPS 333
#define MAXENT  4096

// ---------------- device tables (built per-launch by init kernels) ----------
__device__ float g_cg[27 * 343];                    // dense real CG tensors
__device__ __align__(16) int2 g_e[MAXENT];          // entries: (ysm addr, coeff bits)
__device__ int2  g_desc[NGROUPS];                   // (local out off, J | nnz<<2 | off<<16)

// ---------------- static structure tables -----------------------------------
__constant__ unsigned char TRI_J [27] = {1,1,1, 2,2,2, 3,3, 1,1,1, 2,2,2,2, 3,3,3, 1,1, 2,2,2, 3,3,3,3};
__constant__ unsigned char TRI_L [27] = {1,1,1, 1,1,1, 1,1, 2,2,2, 2,2,2,2, 2,2,2, 3,3, 3,3,3, 3,3,3,3};
__constant__ unsigned char TRI_JO[27] = {0,1,2, 1,2,3, 2,3, 1,2,3, 0,1,2,3, 1,2,3, 2,3, 1,2,3, 0,1,2,3};

__constant__ unsigned char SEG_TYPE[34] = {0,2,2,2,  0,1,2,2,2,2,2,2,2,  0,1,2,2,2,2,2,2,2,2,2,  0,1,2,2,2,2,2,2,2,2};
__constant__ unsigned char SEG_J  [34] = {0,1,2,3,  1,0,1,2,1,2,3,2,3,  2,0,1,2,3,1,2,3,1,2,3,  3,0,2,3,1,2,3,1,2,3};
__constant__ unsigned char SEG_L  [34] = {0,1,2,3,  0,1,1,1,2,2,2,3,3,  0,2,1,1,1,2,2,2,3,3,3,  0,3,1,1,2,2,2,3,3,3};
__constant__ unsigned char SEG_CG [34] = {255,0,11,23, 255,255,1,3,8,12,15,20,24, 255,255,2,4,6,9,13,16,18,21,25, 255,255,5,7,10,14,17,19,22,26};
__constant__ unsigned char SEG_W  [34] = {4,3,2,1,  3,4,3,2,3,2,1,2,1,  2,4,3,2,1,3,2,1,3,2,1,  1,4,2,1,3,2,1,3,2,1};
__constant__ int SEGSTART[4] = {0, 4, 13, 24};
__constant__ int GROW[4]     = {10, 21, 24, 20};
__constant__ int CHJ[4]      = {160, 336, 384, 320};
__constant__ int YOFF[4]     = {0, 4, 13, 23};
__constant__ int COFF[4]     = {0, 16, 64, 144};
__constant__ long long OUT_BASE[4] = {0LL, 1310720LL, 9568256LL, 25296896LL};
__constant__ int PERBV[4]    = {160, 1008, 1920, 2240};

// ---------------- float complex helpers --------------------------------------
struct cf { float x, y; };
__device__ __forceinline__ cf cmulf(cf a, cf b) {
    return cf{a.x * b.x - a.y * b.y, a.x * b.y + a.y * b.x};
}

__device__ __forceinline__ float ffact(int n) {
    float r = 1.0f;
    for (int i = 2; i <= n; i++) r *= (float)i;
    return r;
}

__device__ float su2cgf(int j1, int m1, int j2, int m2, int j3, int m3) {
    if (m3 != m1 + m2) return 0.0f;
    int vmin = max(max(-j1 + j2 + m3, -j1 + m1), 0);
    int vmax = min(min(j2 + j3 + m1, j3 - j1 + j2), j3 + m3);
    if (vmax < vmin) return 0.0f;
    float C = sqrtf((2.0f * j3 + 1.0f) * ffact(j3 + j1 - j2) * ffact(j3 - j1 + j2) *
                    ffact(j1 + j2 - j3) * ffact(j3 + m3) * ffact(j3 - m3) /
                    (ffact(j1 + j2 + j3 + 1) * ffact(j1 - m1) * ffact(j1 + m1) *
                     ffact(j2 - m2) * ffact(j2 + m2)));
    float S = 0.0f;
    for (int v = vmin; v <= vmax; v++) {
        float t = ffact(j2 + j3 + m1 - v) * ffact(j1 - m1 + v) /
                  (ffact(v) * ffact(j3 - j1 + j2 - v) * ffact(j3 + m3 - v) *
                   ffact(v + j1 - j2 - m3));
        if ((v + j2 + m2) & 1) t = -t;
        S += t;
    }
    return C * S;
}

// q_real_to_complex entry: row r (complex m = r-l), col c (real index)
__device__ cf qentf(int l, int r, int c) {
    const float s2 = 0.70710678118654752f;
    int m = r - l;
    float re = 0.0f, im = 0.0f;
    if (m < 0) {
        if (c == l - m)      re = s2;
        else if (c == l + m) im = -s2;
    } else if (m == 0) {
        if (c == l) re = 1.0f;
    } else {
        float sg = (m & 1) ? -1.0f : 1.0f;
        if (c == l + m)      re = sg * s2;
        else if (c == l - m) im = sg * s2;
    }
    float ore, oim;
    switch (l & 3) {               // multiply by (-i)^l
        case 0:  ore = re;  oim = im;  break;
        case 1:  ore = im;  oim = -re; break;
        case 2:  ore = -re; oim = -im; break;
        default: ore = -im; oim = re;  break;
    }
    return cf{ore, oim};
}

// ---------------- init kernel 1: dense real CG tensors (float, 27 blocks) ---
__global__ void shc_init_cg() {
    const int t27 = blockIdx.x;
    const int j = TRI_J[t27], l = TRI_L[t27], J = TRI_JO[t27];
    const int nj = 2 * j + 1, nl = 2 * l + 1, nJ = 2 * J + 1;
    __shared__ float su2[7][7];

    for (int idx = threadIdx.x; idx < nj * nl; idx += blockDim.x) {
        int i = idx / nl, k = idx % nl;
        int m1 = i - j, m2 = k - l, m3 = m1 + m2;
        su2[i][k] = (abs(m3) <= J) ? su2cgf(j, m1, l, m2, J, m3) : 0.0f;
    }
    __syncthreads();

    for (int idx = threadIdx.x; idx < nj * nl * nJ; idx += blockDim.x) {
        int a  = idx / (nl * nJ);
        int r1 = idx % (nl * nJ);
        int b  = r1 / nJ;
        int cc = r1 % nJ;
        float ar = 0.0f;
        for (int i = 0; i < nj; i++) {
            cf q1 = qentf(j, i, a);
            if (q1.x == 0.0f && q1.y == 0.0f) continue;
            for (int k = 0; k < nl; k++) {
                float s = su2[i][k];
                if (s == 0.0f) continue;
                cf q2 = qentf(l, k, b);
                if (q2.x == 0.0f && q2.y == 0.0f) continue;
                int n = J + (i - j) + (k - l);
                cf q3 = qentf(J, n, cc);
                q3.y = -q3.y;                    // conj
                cf tt = cmulf(cmulf(q1, q2), q3);
                ar += tt.x * s;
            }
        }
        g_cg[t27 * 343 + idx] = ar;
    }
}

// ---------------- init kernel 2: compact sparse group table ------------------
// Entry lists padded to even count -> main kernel reads int4 (2 entries/load).
__global__ void shc_build_table() {
    __shared__ int nnzs[NGROUPS];
    __shared__ int offs[NGROUPS];

    const int g = threadIdx.x;
    int J = 0, local = 0;
    int   la[50];
    float lv[50];
    int nnz = 0;

    if (g < NGROUPS) {
        int base;
        if (g < 10)       { J = 0; base = 0;   }
        else if (g < 73)  { J = 1; base = 10;  }
        else if (g < 193) { J = 2; base = 73;  }
        else              { J = 3; base = 193; }
        int idx = g - base;
        int row = idx / GROW[J];
        int gr  = idx % GROW[J];
        int s = SEGSTART[J], accw = 0;
        while (gr >= accw + SEG_W[s]) { accw += SEG_W[s]; s++; }
        int u = gr - accw;
        local = row * CHJ[J] + gr * 16;

        int type = SEG_TYPE[s];
        if (type == 0) {            // l=0 copy, j=J
            la[0] = (YOFF[J] + row * (4 - J) + u) * 256;
            lv[0] = 1.0f;
            nnz = 1;
        } else if (type == 1) {     // j=0 copy, l=J
            la[0] = u * 256 + COFF[J] + row * 16;
            lv[0] = 1.0f;
            nnz = 1;
        } else {
            int jj = SEG_J[s], ll = SEG_L[s];
            const float* C = g_cg + (int)SEG_CG[s] * 343;
            int nj = 2 * jj + 1, nl2 = 2 * ll + 1, nJ = 2 * J + 1;
            for (int n = 0; n < nj; n++)
                for (int m = 0; m < nl2; m++) {
                    float v = C[(n * nl2 + m) * nJ + row];
                    if (fabsf(v) > 1e-6f) {
                        la[nnz] = (YOFF[jj] + n * (4 - jj) + u) * 256 +
                                  COFF[ll] + m * 16;
                        lv[nnz] = v;
                        nnz++;
                    }
                }
        }
        if (nnz & 1) { la[nnz] = 0; lv[nnz] = 0.0f; nnz++; }   // pad to even
        nnzs[g] = nnz;
    }
    __syncthreads();
    if (threadIdx.x == 0) {
        int acc = 0;
        for (int i = 0; i < NGROUPS; i++) { offs[i] = acc; acc += nnzs[i]; }
    }
    __syncthreads();
    if (g < NGROUPS) {
        int off = offs[g];                       // even (sum of evens)
        for (int k = 0; k < nnz; k++)
            g_e[off + k] = make_int2(la[k], __float_as_int(lv[k]));
        g_desc[g] = make_int2(local, J | (nnz << 2) | (off << 16));
    }
}

// ---------------- main fused kernel -----------------------------------------
// smem: ysm padded to 32*256 floats (32 KB). During stage 1 the first 8192 B
// alias ksm[32][32] float2-duplicated K (y padded to 32 with zeros) and the
// next 128 B hold nrow; barrier before overwriting with ysm rows.
__global__ void __launch_bounds__(256, 4)
shc_main(const float* __restrict__ x0, const float* __restrict__ x1,
         const float* __restrict__ x2, const float* __restrict__ x3,
         const int*  __restrict__ pidx, const float* __restrict__ kern,
         float* __restrict__ out)
{
    __shared__ __align__(16) char smraw[32 * 256 * 4];
    float*  ysm  = reinterpret_cast<float*>(smraw);
    float2* ksm  = reinterpret_cast<float2*>(smraw);           // [p][y] dup (k,k)
    int*    nrow = reinterpret_cast<int*>(smraw + 8192);       // 32 ints

    const int t  = threadIdx.x;
    const int bv = blockIdx.x;

    // load K (32x30) duplicated into pairs; zero the padding y = 30,31
    const float* kb = kern + (long long)bv * 960;
    #pragma unroll
    for (int i = 0; i < 4; i++) {
        int idx = t + i * 256;
        if (idx < 960) {
            float v = kb[idx];
            int p = idx / 30, y = idx - p * 30;
            ksm[p * 32 + y] = make_float2(v, v);
        }
    }
    if (t < 64) ksm[(t >> 1) * 32 + 30 + (t & 1)] = make_float2(0.0f, 0.0f);
    if (t >= 224) {   // 32 threads load patch indices
        int i = t - 224;
        int2 pr = ((const int2*)pidx)[(long long)bv * 32 + i];
        nrow[i] = pr.x * 4096 + pr.y;
    }
    __syncthreads();

    // thread -> (channel pair, y-half)
    const int q  = t & 127;          // 0..127
    const int c  = q * 2;            // channel pair base
    const int h2 = t >> 7;           // 0: y 0..15, 1: y 16..31
    const int ybase = h2 * 16;

    const float* src; int chl;
    if (c < 16)       { src = x0 + c;         chl = 16;  }
    else if (c < 64)  { src = x1 + (c - 16);  chl = 48;  }
    else if (c < 144) { src = x2 + (c - 64);  chl = 80;  }
    else              { src = x3 + (c - 144); chl = 112; }

    unsigned long long acc[16];
    #pragma unroll
    for (int y = 0; y < 16; y++) acc[y] = 0ull;

    // depth-2 pipelined gather + packed FMA over this thread's 16 y's
    unsigned long long s0 = *reinterpret_cast<const unsigned long long*>(
                                src + (long long)nrow[0] * chl);
    unsigned long long s1 = *reinterpret_cast<const unsigned long long*>(
                                src + (long long)nrow[1] * chl);
    #pragma unroll 2
    for (int p = 0; p < 32; p += 2) {
        unsigned long long a = s0, b = s1;
        if (p + 2 < 32) {
            s0 = *reinterpret_cast<const unsigned long long*>(
                     src + (long long)nrow[p + 2] * chl);
            s1 = *reinterpret_cast<const unsigned long long*>(
                     src + (long long)nrow[p + 3] * chl);
        }
        const ulonglong2* kpa =
            reinterpret_cast<const ulonglong2*>(&ksm[p * 32 + ybase]);
        const ulonglong2* kpb =
            reinterpret_cast<const ulonglong2*>(&ksm[(p + 1) * 32 + ybase]);
        #pragma unroll
        for (int h = 0; h < 8; h++) {
            ulonglong2 k2 = kpa[h];
            asm("fma.rn.f32x2 %0, %1, %2, %0;" : "+l"(acc[2 * h])     : "l"(a), "l"(k2.x));
            asm("fma.rn.f32x2 %0, %1, %2, %0;" : "+l"(acc[2 * h + 1]) : "l"(a), "l"(k2.y));
        }
        #pragma unroll
        for (int h = 0; h < 8; h++) {
            ulonglong2 k2 = kpb[h];
            asm("fma.rn.f32x2 %0, %1, %2, %0;" : "+l"(acc[2 * h])     : "l"(b), "l"(k2.x));
            asm("fma.rn.f32x2 %0, %1, %2, %0;" : "+l"(acc[2 * h + 1]) : "l"(b), "l"(k2.y));
        }
    }

    __syncthreads();   // all ksm/nrow reads done — safe to overwrite with ysm

    #pragma unroll
    for (int y = 0; y < 16; y++)
        *reinterpret_cast<unsigned long long*>(&ysm[(ybase + y) * 256 + c]) = acc[y];
    __syncthreads();

    // stage 2: sparse CG contraction + copies (int4 = 2 entries per load)
    const int ch = t & 15;
    const int4* e4 = reinterpret_cast<const int4*>(g_e);
    for (int g = (t >> 4); g < NGROUPS; g += 16) {
        int2 d = __ldg(&g_desc[g]);
        int J     = d.y & 3;
        int npair = ((d.y >> 2) & 63) >> 1;
        int base4 = (d.y >> 16) >> 1;
        float v = 0.0f;
        int k = 0;
        for (; k + 2 <= npair; k += 2) {
            int4 pA = __ldg(&e4[base4 + k]);
            int4 pB = __ldg(&e4[base4 + k + 1]);
            float v0 = __int_as_float(pA.y) * ysm[pA.x + ch];
            float v1 = __int_as_float(pA.w) * ysm[pA.z + ch];
            v0 = fmaf(__int_as_float(pB.y), ysm[pB.x + ch], v0);
            v1 = fmaf(__int_as_float(pB.w), ysm[pB.z + ch], v1);
            v += v0 + v1;
        }
        if (k < npair) {
            int4 pA = __ldg(&e4[base4 + k]);
            v = fmaf(__int_as_float(pA.y), ysm[pA.x + ch], v);
            v = fmaf(__int_as_float(pA.w), ysm[pA.z + ch], v);
        }
        out[OUT_BASE[J] + (long long)bv * PERBV[J] + d.x + ch] = v;
    }
}

// ---------------- launch -----------------------------------------------------
extern "C" void kernel_launch(void* const* d_in, const int* in_sizes, int n_in,
                              void* d_out, int out_size)
{
    const float* x0   = (const float*)d_in[0];
    const float* x1   = (const float*)d_in[1];
    const float* x2   = (const float*)d_in[2];
    const float* x3   = (const float*)d_in[3];
    const int*   pidx = (const int*)  d_in[4];
    const float* kern = (const float*)d_in[5];
    float* out = (float*)d_out;

    shc_init_cg<<<27, 128>>>();
    shc_build_table<<<1, 352>>>();
    shc_main<<<NBV, 256>>>(x0, x1, x2, x3, pidx, kern, out);
}